// round 10
// baseline (speedup 1.0000x reference)
#include <cuda_runtime.h>
#include <cstdint>

// x: [B=16, C=8, T=262144] fp32 row-major.
// out = x * (c == 0 ? 1.0f : 0.5f)
//
// Final shape-matrix cell: block-contiguous 64 KB tiles + deep per-thread
// batching (4 x 256-bit = 128 B/thread), combining the row-locality of the
// R4/R6 winner with R2-style front-batched MLP, minus R3's scatter.
//
// Units: float8 (32 B). Tile = 2048 vec8 = 64 KB. Channel row = 32768 vec8
// = 16 tiles, so channel is uniform per block:
//   channel = (blockIdx.x >> 4) & 7.

static constexpr long long N_VEC8  = (16LL * 8LL * 262144LL) / 8;  // 4,194,304
static constexpr int       THREADS = 512;
static constexpr int       UNROLL  = 4;
static constexpr int       TILE    = THREADS * UNROLL;             // 2048 vec8 = 64 KB
static constexpr int       BLOCKS  = (int)(N_VEC8 / TILE);         // 2048, exact

struct alignas(32) f8 { float v[8]; };

__device__ __forceinline__ f8 ldg256(const f8* p) {
    f8 r;
    asm volatile(
        "ld.global.nc.v8.f32 {%0, %1, %2, %3, %4, %5, %6, %7}, [%8];"
        : "=f"(r.v[0]), "=f"(r.v[1]), "=f"(r.v[2]), "=f"(r.v[3]),
          "=f"(r.v[4]), "=f"(r.v[5]), "=f"(r.v[6]), "=f"(r.v[7])
        : "l"(p));
    return r;
}

__device__ __forceinline__ void stg256(f8* p, const f8& r) {
    asm volatile(
        "st.global.v8.f32 [%0], {%1, %2, %3, %4, %5, %6, %7, %8};"
        :: "l"(p),
           "f"(r.v[0]), "f"(r.v[1]), "f"(r.v[2]), "f"(r.v[3]),
           "f"(r.v[4]), "f"(r.v[5]), "f"(r.v[6]), "f"(r.v[7])
        : "memory");
}

__global__ void __launch_bounds__(THREADS) channel_scale_kernel(
    const f8* __restrict__ x, f8* __restrict__ out)
{
    // Per-block uniform channel scale: channel = (blockIdx.x >> 4) & 7.
    const float s = ((blockIdx.x & (7u << 4)) == 0u) ? 1.0f : 0.5f;

    const long long base = (long long)blockIdx.x * TILE + threadIdx.x;

    f8 a[UNROLL];
#pragma unroll
    for (int k = 0; k < UNROLL; k++) {
        a[k] = ldg256(&x[base + k * THREADS]);
    }

#pragma unroll
    for (int k = 0; k < UNROLL; k++) {
#pragma unroll
        for (int j = 0; j < 8; j++) a[k].v[j] *= s;
        stg256(&out[base + k * THREADS], a[k]);
    }
}

extern "C" void kernel_launch(void* const* d_in, const int* in_sizes, int n_in,
                              void* d_out, int out_size)
{
    const f8* x = (const f8*)d_in[0];
    f8* out = (f8*)d_out;
    channel_scale_kernel<<<BLOCKS, THREADS>>>(x, out);
}

// round 11
// speedup vs baseline: 1.0173x; 1.0173x over previous
#include <cuda_runtime.h>
#include <cstdint>

// x: [B=16, C=8, T=262144] fp32 row-major.
// out = x * (c == 0 ? 1.0f : 0.5f)
//
// FINAL kernel (session optimum, R6/R8 configuration):
//   - block-contiguous 32 KB tiles (4096 independent blocks -> max concurrent
//     request streams, best DRAM row locality)
//   - 512 threads, 2 x 256-bit (v8.f32) loads/stores per thread (64 B/thread)
//   - per-block uniform channel scale (zero per-element index ALU)
//
// Measured: 43.49 us bench / 35.6 us ncu, DRAM 75.3%, 5.96 TB/s bus
// (~7.4 TB/s logical incl. L2 write retention) = GB300 mixed-R/W streaming
// wall. Tested worse/neutral: grid-wide striding, MLP 4/8, persistent grid,
// 64 KB tiles, all L2 eviction policies, __ldcs/__stcs.
//
// Units: float8 (32 B). Channel row = T/8 = 32768 vec8 = 32 tiles of 1024,
// so channel is uniform per block: channel = (blockIdx.x >> 5) & 7.

static constexpr long long N_VEC8  = (16LL * 8LL * 262144LL) / 8;  // 4,194,304
static constexpr int       THREADS = 512;
static constexpr int       UNROLL  = 2;
static constexpr int       TILE    = THREADS * UNROLL;             // 1024 vec8 = 32 KB
static constexpr int       BLOCKS  = (int)(N_VEC8 / TILE);         // 4096, exact

struct alignas(32) f8 { float v[8]; };

__device__ __forceinline__ f8 ldg256(const f8* p) {
    f8 r;
    asm volatile(
        "ld.global.nc.v8.f32 {%0, %1, %2, %3, %4, %5, %6, %7}, [%8];"
        : "=f"(r.v[0]), "=f"(r.v[1]), "=f"(r.v[2]), "=f"(r.v[3]),
          "=f"(r.v[4]), "=f"(r.v[5]), "=f"(r.v[6]), "=f"(r.v[7])
        : "l"(p));
    return r;
}

__device__ __forceinline__ void stg256(f8* p, const f8& r) {
    asm volatile(
        "st.global.v8.f32 [%0], {%1, %2, %3, %4, %5, %6, %7, %8};"
        :: "l"(p),
           "f"(r.v[0]), "f"(r.v[1]), "f"(r.v[2]), "f"(r.v[3]),
           "f"(r.v[4]), "f"(r.v[5]), "f"(r.v[6]), "f"(r.v[7])
        : "memory");
}

__global__ void __launch_bounds__(THREADS) channel_scale_kernel(
    const f8* __restrict__ x, f8* __restrict__ out)
{
    // Per-block uniform channel scale: channel = (blockIdx.x >> 5) & 7.
    const float s = ((blockIdx.x & (7u << 5)) == 0u) ? 1.0f : 0.5f;

    const long long base = (long long)blockIdx.x * TILE + threadIdx.x;

    f8 a[UNROLL];
#pragma unroll
    for (int k = 0; k < UNROLL; k++) {
        a[k] = ldg256(&x[base + k * THREADS]);
    }

#pragma unroll
    for (int k = 0; k < UNROLL; k++) {
#pragma unroll
        for (int j = 0; j < 8; j++) a[k].v[j] *= s;
        stg256(&out[base + k * THREADS], a[k]);
    }
}

extern "C" void kernel_launch(void* const* d_in, const int* in_sizes, int n_in,
                              void* d_out, int out_size)
{
    const f8* x = (const f8*)d_in[0];
    f8* out = (f8*)d_out;
    channel_scale_kernel<<<BLOCKS, THREADS>>>(x, out);
}